// round 7
// baseline (speedup 1.0000x reference)
#include <cuda_runtime.h>
#include <math.h>

#define BB 1323u            // batch == NPTS
#define DM 1024             // DMODEL
#define NTOT (BB * BB)      // 1,750,329 points
#define NCHUNK ((NTOT + 3) / 4)   // 437,583 4-point chunks
#define NBLK 1184u
#define TPB 256u
#define TTOT (NBLK * TPB)         // 303,104 threads
#define NPBLK 148u                // params blocks (one per SM in wave 1)
#define LOG_2PI 1.8378770664093453f

__device__ __align__(16) float g_params[BB * 16];
__device__ int g_flag;            // rows published (0..1323)
__device__ unsigned g_done;       // blocks finished (for reset)

__device__ __forceinline__ float softplus_f(float x) {
    return fmaxf(x, 0.0f) + log1pf(__expf(-fabsf(x)));
}

// ---------- warp-collective: compute params for one row, publish ----------
__device__ __forceinline__ void compute_row(unsigned row, int lane,
                                            const float4* __restrict__ rep4,
                                            const float4* __restrict__ Wm4,
                                            const float4* __restrict__ Ws4,
                                            const float* __restrict__ bm,
                                            const float* __restrict__ bs,
                                            float* __restrict__ out)
{
    float acc[9];
    #pragma unroll
    for (int a = 0; a < 9; a++) acc[a] = 0.0f;

    const float4* r4 = rep4 + (size_t)row * (DM / 4);
    #pragma unroll
    for (int c = 0; c < 8; c++) {
        int idx = c * 32 + lane;
        float4 rv = r4[idx];
        #pragma unroll
        for (int a = 0; a < 3; a++) {
            float4 w = Wm4[a * (DM / 4) + idx];
            acc[a] = fmaf(rv.x, w.x, fmaf(rv.y, w.y, fmaf(rv.z, w.z, fmaf(rv.w, w.w, acc[a]))));
        }
        #pragma unroll
        for (int a = 0; a < 6; a++) {
            float4 w = Ws4[a * (DM / 4) + idx];
            acc[3 + a] = fmaf(rv.x, w.x, fmaf(rv.y, w.y, fmaf(rv.z, w.z, fmaf(rv.w, w.w, acc[3 + a]))));
        }
    }

    #pragma unroll
    for (int a = 0; a < 9; a++) {
        #pragma unroll
        for (int off = 16; off > 0; off >>= 1)
            acc[a] += __shfl_down_sync(0xffffffffu, acc[a], off);
    }

    if (lane == 0) {
        float mx  = acc[0] + bm[0];
        float my  = acc[1] + bm[1];
        float mz  = acc[2] + bm[2];
        float L00 = softplus_f(acc[3] + bs[0]);
        float L10 = acc[4] + bs[1];
        float L11 = softplus_f(acc[5] + bs[2]);
        float L20 = acc[6] + bs[3];
        float L21 = acc[7] + bs[4];
        float L22 = softplus_f(acc[8] + bs[5]);

        float c = -(logf(L00) + logf(L11) + logf(L22)) - 1.5f * LOG_2PI;

        float4* P = (float4*)(g_params + (size_t)row * 16);
        P[0] = make_float4(mx, my, mz, 1.0f / L00);
        P[1] = make_float4(L10, 1.0f / L11, L20, L21);
        P[2] = make_float4(1.0f / L22, c, 0.0f, 0.0f);

        float* Lout = out + (size_t)NTOT + (size_t)row * 9;
        Lout[0] = L00; Lout[1] = 0.0f; Lout[2] = 0.0f;
        Lout[3] = L10; Lout[4] = L11; Lout[5] = 0.0f;
        Lout[6] = L20; Lout[7] = L21; Lout[8] = L22;

        __threadfence();
        atomicAdd(&g_flag, 1);
    }
}

// ---------- profile math ----------
__device__ __forceinline__ float mvn_eval(float d0, float d1, float d2,
                                          const float4& P0, const float4& P1,
                                          const float4& P2)
{
    float y0 = (d0 - P0.x) * P0.w;
    float y1 = (d1 - P0.y - P1.x * y0) * P1.y;
    float y2 = (d2 - P0.z - P1.z * y0 - P1.w * y1) * P2.x;
    float M  = fmaf(y0, y0, fmaf(y1, y1, y2 * y2));
    return __expf(fmaf(-0.5f, M, P2.y));
}

__device__ __forceinline__ void chunk_eval(unsigned p0, const float* d,
                                           float* __restrict__ out)
{
    unsigned i = p0 / BB;
    unsigned j = p0 - i * BB;
    const float4* P = (const float4*)(g_params + (size_t)i * 16);
    float4 P0 = P[0], P1 = P[1], P2 = P[2];

    float4 res;
    float* rp = &res.x;
    #pragma unroll
    for (int k = 0; k < 4; k++) {
        if (j >= BB) {
            j -= BB;
            P = (const float4*)(g_params + (size_t)(++i) * 16);
            P0 = P[0]; P1 = P[1]; P2 = P[2];
        }
        rp[k] = mvn_eval(d[3*k], d[3*k+1], d[3*k+2], P0, P1, P2);
        j++;
    }
    *(float4*)(out + p0) = res;
}

__device__ __forceinline__ void tail_eval(unsigned pStart,
                                          const float* __restrict__ dxyz,
                                          float* __restrict__ out)
{
    for (unsigned p = pStart; p < NTOT; p++) {
        unsigned i = p / BB;
        const float4* P = (const float4*)(g_params + (size_t)i * 16);
        out[p] = mvn_eval(dxyz[3*p], dxyz[3*p+1], dxyz[3*p+2], P[0], P[1], P[2]);
    }
}

// ---------- fused kernel ----------
__global__ __launch_bounds__(TPB)
void mvn3d_fused_kernel(const float* __restrict__ rep,
                        const float* __restrict__ dxyz,
                        const float* __restrict__ Wm,
                        const float* __restrict__ bm,
                        const float* __restrict__ Ws,
                        const float* __restrict__ bs,
                        float* __restrict__ out)
{
    const unsigned bid = blockIdx.x;
    const unsigned tid = threadIdx.x;
    const unsigned t   = bid * TPB + tid;

    const unsigned pA = t * 4;
    const unsigned pB = (t + TTOT) * 4;
    const bool hasB  = (t + TTOT < NCHUNK);
    const bool fullA = (pA + 3 < NTOT);
    const bool fullB = hasB && (pB + 3 < NTOT);

    float4 vA[3], vB[3];

    if (bid >= NPBLK) {
        // waiter blocks: front-batch dxyz loads to overlap DRAM with params compute
        if (fullA) {
            const float4* dv = (const float4*)(dxyz + (size_t)pA * 3);
            vA[0] = dv[0]; vA[1] = dv[1]; vA[2] = dv[2];
        }
        if (fullB) {
            const float4* dv = (const float4*)(dxyz + (size_t)pB * 3);
            vB[0] = dv[0]; vB[1] = dv[1]; vB[2] = dv[2];
        }
    } else {
        // params blocks: warp-per-row, rows bid + 148k
        const int warp = tid >> 5;
        const int lane = tid & 31;
        const float4* rep4 = (const float4*)rep;
        const float4* Wm4  = (const float4*)Wm;
        const float4* Ws4  = (const float4*)Ws;

        unsigned row = bid + NPBLK * (unsigned)warp;          // <= 147+1036 = 1183
        compute_row(row, lane, rep4, Wm4, Ws4, bm, bs, out);
        if (warp == 7) {
            unsigned row2 = bid + NPBLK * 8u;                 // 1184 + bid
            if (row2 < BB)
                compute_row(row2, lane, rep4, Wm4, Ws4, bm, bs, out);
        }

        // now load our own profile chunks
        if (fullA) {
            const float4* dv = (const float4*)(dxyz + (size_t)pA * 3);
            vA[0] = dv[0]; vA[1] = dv[1]; vA[2] = dv[2];
        }
        if (fullB) {
            const float4* dv = (const float4*)(dxyz + (size_t)pB * 3);
            vB[0] = dv[0]; vB[1] = dv[1]; vB[2] = dv[2];
        }
    }

    // wait until all 1323 param rows are published (one poller per block)
    if (tid == 0) {
        while (*(volatile int*)&g_flag < (int)BB)
            __nanosleep(64);
        __threadfence();
    }
    __syncthreads();

    if (fullA)           chunk_eval(pA, (const float*)vA, out);
    else if (pA < NTOT)  tail_eval(pA, dxyz, out);

    if (fullB)                   chunk_eval(pB, (const float*)vB, out);
    else if (hasB && pB < NTOT)  tail_eval(pB, dxyz, out);

    // reset flags for the next graph replay (last block to finish does it)
    __syncthreads();
    if (tid == 0) {
        unsigned d = atomicAdd(&g_done, 1u);
        if (d == NBLK - 1u) {
            g_flag = 0;
            g_done = 0u;
        }
    }
}

extern "C" void kernel_launch(void* const* d_in, const int* in_sizes, int n_in,
                              void* d_out, int out_size) {
    const float* rep  = (const float*)d_in[0];
    const float* dxyz = (const float*)d_in[1];
    const float* Wm   = (const float*)d_in[2];
    const float* bm   = (const float*)d_in[3];
    const float* Ws   = (const float*)d_in[4];
    const float* bs   = (const float*)d_in[5];
    float* out = (float*)d_out;

    mvn3d_fused_kernel<<<NBLK, TPB>>>(rep, dxyz, Wm, bm, Ws, bs, out);
}

// round 8
// speedup vs baseline: 2.5309x; 2.5309x over previous
#include <cuda_runtime.h>
#include <math.h>

#define BB 1323u            // batch == NPTS
#define DM 1024             // DMODEL
#define NTOT (BB * BB)      // 1,750,329 points
#define NCHUNK ((NTOT + 3) / 4)   // 437,583 4-point chunks
#define NBLK 1184u
#define TPB 256u
#define TTOT (NBLK * TPB)         // 303,104 threads
#define LOG_2PI 1.8378770664093453f

__device__ __align__(16) float g_params[BB * 16];

__device__ __forceinline__ float softplus_f(float x) {
    return fmaxf(x, 0.0f) + log1pf(__expf(-fabsf(x)));
}

// ---------------- kernel 1: params. 148 blocks x 9 warps (one block/SM) ----------------
__global__ __launch_bounds__(288)
void mvn3d_params_kernel(const float* __restrict__ rep,
                         const float* __restrict__ Wm,
                         const float* __restrict__ bm,
                         const float* __restrict__ Ws,
                         const float* __restrict__ bs,
                         float* __restrict__ out)
{
#if __CUDA_ARCH__ >= 900
    // release the dependent profile kernel immediately (PDL)
    cudaTriggerProgrammaticLaunchCompletion();
#endif

    __shared__ __align__(16) float sW[9 * DM];       // 36 KB
    float4* sW4 = (float4*)sW;

    const int tid  = threadIdx.x;
    const int warp = tid >> 5;
    const int lane = tid & 31;

    // cooperative weight load: 2304 float4, 8 per thread
    {
        const float4* Wm4 = (const float4*)Wm;   // 768 float4
        const float4* Ws4 = (const float4*)Ws;   // 1536 float4
        #pragma unroll
        for (int c = 0; c < 8; c++) {
            int t2 = c * 288 + tid;
            sW4[t2] = (t2 < 768) ? Wm4[t2] : Ws4[t2 - 768];
        }
    }
    __syncthreads();

    // rows: warp 0..7 -> warp*148 + bid (<=1183); warp 8 -> 1184 + bid (if < 1323)
    unsigned row = (unsigned)warp * 148u + blockIdx.x;
    if (warp == 8) row = 1184u + blockIdx.x;
    if (row >= BB) return;

    float acc[9];
    #pragma unroll
    for (int a = 0; a < 9; a++) acc[a] = 0.0f;

    const float4* r4 = (const float4*)(rep + (size_t)row * DM);
    #pragma unroll 2
    for (int c = 0; c < 8; c++) {
        int idx = c * 32 + lane;
        float4 rv = r4[idx];
        #pragma unroll
        for (int a = 0; a < 9; a++) {
            float4 w = sW4[a * 256 + idx];
            acc[a] = fmaf(rv.x, w.x, fmaf(rv.y, w.y, fmaf(rv.z, w.z, fmaf(rv.w, w.w, acc[a]))));
        }
    }

    #pragma unroll
    for (int a = 0; a < 9; a++) {
        #pragma unroll
        for (int off = 16; off > 0; off >>= 1)
            acc[a] += __shfl_down_sync(0xffffffffu, acc[a], off);
    }

    if (lane == 0) {
        float mx  = acc[0] + bm[0];
        float my  = acc[1] + bm[1];
        float mz  = acc[2] + bm[2];
        float L00 = softplus_f(acc[3] + bs[0]);
        float L10 = acc[4] + bs[1];
        float L11 = softplus_f(acc[5] + bs[2]);
        float L20 = acc[6] + bs[3];
        float L21 = acc[7] + bs[4];
        float L22 = softplus_f(acc[8] + bs[5]);

        float c = -(logf(L00) + logf(L11) + logf(L22)) - 1.5f * LOG_2PI;

        float4* P = (float4*)(g_params + (size_t)row * 16);
        P[0] = make_float4(mx, my, mz, 1.0f / L00);
        P[1] = make_float4(L10, 1.0f / L11, L20, L21);
        P[2] = make_float4(1.0f / L22, c, 0.0f, 0.0f);

        float* Lout = out + (size_t)NTOT + (size_t)row * 9;
        Lout[0] = L00; Lout[1] = 0.0f; Lout[2] = 0.0f;
        Lout[3] = L10; Lout[4] = L11; Lout[5] = 0.0f;
        Lout[6] = L20; Lout[7] = L21; Lout[8] = L22;
    }
}

// ---------------- kernel 2: profile (PDL secondary) ----------------
__device__ __forceinline__ float mvn_eval(float d0, float d1, float d2,
                                          const float4& P0, const float4& P1,
                                          const float4& P2)
{
    float y0 = (d0 - P0.x) * P0.w;
    float y1 = (d1 - P0.y - P1.x * y0) * P1.y;
    float y2 = (d2 - P0.z - P1.z * y0 - P1.w * y1) * P2.x;
    float M  = fmaf(y0, y0, fmaf(y1, y1, y2 * y2));
    return __expf(fmaf(-0.5f, M, P2.y));
}

__device__ __forceinline__ void chunk_eval(unsigned p0, const float* d,
                                           float* __restrict__ out)
{
    unsigned i = p0 / BB;
    unsigned j = p0 - i * BB;
    const float4* P = (const float4*)(g_params + (size_t)i * 16);
    float4 P0 = P[0], P1 = P[1], P2 = P[2];

    float4 res;
    float* rp = &res.x;
    #pragma unroll
    for (int k = 0; k < 4; k++) {
        if (j >= BB) {
            j -= BB;
            P = (const float4*)(g_params + (size_t)(++i) * 16);
            P0 = P[0]; P1 = P[1]; P2 = P[2];
        }
        rp[k] = mvn_eval(d[3*k], d[3*k+1], d[3*k+2], P0, P1, P2);
        j++;
    }
    *(float4*)(out + p0) = res;
}

__device__ __forceinline__ void tail_eval(unsigned pStart,
                                          const float* __restrict__ dxyz,
                                          float* __restrict__ out)
{
    for (unsigned p = pStart; p < NTOT; p++) {
        unsigned i = p / BB;
        const float4* P = (const float4*)(g_params + (size_t)i * 16);
        out[p] = mvn_eval(dxyz[3*p], dxyz[3*p+1], dxyz[3*p+2], P[0], P[1], P[2]);
    }
}

__global__ __launch_bounds__(TPB)
void mvn3d_profile_kernel(const float* __restrict__ dxyz,
                          float* __restrict__ out)
{
    const unsigned t = blockIdx.x * TPB + threadIdx.x;

    const unsigned pA = t * 4;                 // chunk 0
    const unsigned pB = (t + TTOT) * 4;        // chunk 1 (may not exist)

    const bool hasB  = (t + TTOT < NCHUNK);
    const bool fullA = (pA + 3 < NTOT);
    const bool fullB = hasB && (pB + 3 < NTOT);

    // front-batch dxyz loads — overlaps with the still-running params kernel
    float4 vA[3], vB[3];
    if (fullA) {
        const float4* dv = (const float4*)(dxyz + (size_t)pA * 3);
        vA[0] = dv[0]; vA[1] = dv[1]; vA[2] = dv[2];
    }
    if (fullB) {
        const float4* dv = (const float4*)(dxyz + (size_t)pB * 3);
        vB[0] = dv[0]; vB[1] = dv[1]; vB[2] = dv[2];
    }

#if __CUDA_ARCH__ >= 900
    // wait for the params kernel to fully complete (memory visible)
    cudaGridDependencySynchronize();
#endif

    if (fullA)           chunk_eval(pA, (const float*)vA, out);
    else if (pA < NTOT)  tail_eval(pA, dxyz, out);

    if (fullB)                   chunk_eval(pB, (const float*)vB, out);
    else if (hasB && pB < NTOT)  tail_eval(pB, dxyz, out);
}

extern "C" void kernel_launch(void* const* d_in, const int* in_sizes, int n_in,
                              void* d_out, int out_size) {
    const float* rep  = (const float*)d_in[0];
    const float* dxyz = (const float*)d_in[1];
    const float* Wm   = (const float*)d_in[2];
    const float* bm   = (const float*)d_in[3];
    const float* Ws   = (const float*)d_in[4];
    const float* bs   = (const float*)d_in[5];
    float* out = (float*)d_out;

    mvn3d_params_kernel<<<148, 288>>>(rep, Wm, bm, Ws, bs, out);

    // dependent launch: overlaps its load phase with the params kernel
    cudaLaunchConfig_t cfg = {};
    cfg.gridDim  = dim3(NBLK);
    cfg.blockDim = dim3(TPB);
    cudaLaunchAttribute attr[1];
    attr[0].id = cudaLaunchAttributeProgrammaticStreamSerialization;
    attr[0].val.programmaticStreamSerializationAllowed = 1;
    cfg.attrs = attr;
    cfg.numAttrs = 1;
    cudaLaunchKernelEx(&cfg, mvn3d_profile_kernel, dxyz, out);
}